// round 14
// baseline (speedup 1.0000x reference)
#include <cuda_runtime.h>
#include <cuda_bf16.h>
#include <cuda_fp16.h>
#include <stdint.h>

#define N_NODES 100000
#define E_EDGES 1600000
#define F_HID   128
#define F_OUT   64
#define SCAN_B  98   // ceil(N_NODES / 1024)

// ---------------- scratch (static device arrays; no allocations) ----------------
__device__ __align__(256) float  g_h[(size_t)N_NODES * F_HID];    // fp32 h (layer 3 only)
__device__ __align__(256) __half g_h16[(size_t)N_NODES * F_HID];  // fp16 h (layers 1-2)
__device__ __align__(256) float  g_agg[(size_t)N_NODES * F_HID];
__device__ __align__(256) float  g_dinv[N_NODES];
__device__ __align__(256) float  g_nrm[E_EDGES];
__device__ __align__(256) int    g_col[E_EDGES];
__device__ __align__(256) int    g_row[N_NODES + 1];
__device__ __align__(256) int    g_deg_i[N_NODES];
__device__ __align__(256) int    g_cur[N_NODES];
__device__ __align__(256) int    g_bsum[SCAN_B];
__device__ __align__(256) int    g_boff[SCAN_B];
// W in mma-fragment order, 16 ktiles (0-7: Wh, 8-15: Wl).
__device__ __align__(256) unsigned g_wf[3][16 * 16 * 64];
__device__ int g_is64;

__device__ __forceinline__ void hilo(float w, __nv_bfloat16& h, __nv_bfloat16& l) {
    h = __float2bfloat16(w);
    l = __float2bfloat16(w - __bfloat162float(h));
}
__device__ __forceinline__ uint32_t pack2(__nv_bfloat16 a, __nv_bfloat16 b) {
    return ((uint32_t)__bfloat16_as_ushort(b) << 16) | __bfloat16_as_ushort(a);
}

#define MMA16816(acc, a, bx, by) \
    asm volatile( \
        "mma.sync.aligned.m16n8k16.row.col.f32.bf16.bf16.f32 " \
        "{%0,%1,%2,%3}, {%4,%5,%6,%7}, {%8,%9}, {%0,%1,%2,%3};" \
        : "+f"((acc)[0]), "+f"((acc)[1]), "+f"((acc)[2]), "+f"((acc)[3]) \
        : "r"((a)[0]), "r"((a)[1]), "r"((a)[2]), "r"((a)[3]), "r"(bx), "r"(by))

// ---------------- edge dtype detection ----------------
__global__ void k_detect(const int* __restrict__ w) {
    int lane = threadIdx.x;
    int acc = 0;
    for (int i = 1 + 2 * lane; i < 4096; i += 64) acc |= w[i];
    #pragma unroll
    for (int o = 16; o; o >>= 1) acc |= __shfl_xor_sync(0xffffffffu, acc, o);
    if (lane == 0) g_is64 = (acc == 0) ? 1 : 0;
}
__device__ __forceinline__ int edge_at(const void* ei, long long idx) {
    int v = g_is64 ? (int)((const long long*)ei)[idx] : ((const int*)ei)[idx];
    v = v < 0 ? 0 : v;
    return v >= N_NODES ? N_NODES - 1 : v;
}

// ---------------- CSR build ----------------
__global__ void k_zero() {
    int i = blockIdx.x * blockDim.x + threadIdx.x;
    if (i < N_NODES) { g_deg_i[i] = 0; g_cur[i] = 0; }
}
__global__ void k_hist(const void* __restrict__ ei) {
    int e = blockIdx.x * blockDim.x + threadIdx.x;
    if (e < E_EDGES) atomicAdd(&g_deg_i[edge_at(ei, (long long)E_EDGES + e)], 1);
}
__global__ __launch_bounds__(1024) void k_scan1() {
    const int t = threadIdx.x;
    const int i = blockIdx.x * 1024 + t;
    const int lane = t & 31, warp = t >> 5;
    int d = (i < N_NODES) ? g_deg_i[i] : 0;
    int v = d;
    #pragma unroll
    for (int o = 1; o < 32; o <<= 1) {
        int n = __shfl_up_sync(0xffffffffu, v, o);
        if (lane >= o) v += n;
    }
    __shared__ int wsum[32];
    if (lane == 31) wsum[warp] = v;
    __syncthreads();
    if (warp == 0) {
        int s = wsum[lane];
        #pragma unroll
        for (int o = 1; o < 32; o <<= 1) {
            int n = __shfl_up_sync(0xffffffffu, s, o);
            if (lane >= o) s += n;
        }
        wsum[lane] = s;
    }
    __syncthreads();
    int excl = v - d + (warp > 0 ? wsum[warp - 1] : 0);
    if (i < N_NODES) {
        g_row[i] = excl;
        g_dinv[i] = rsqrtf((float)(d + 1));
    }
    if (t == 1023) g_bsum[blockIdx.x] = excl + d;
}
__global__ void k_scan2() {
    __shared__ int s[SCAN_B];
    int t = threadIdx.x;
    if (t < SCAN_B) s[t] = g_bsum[t];
    __syncthreads();
    if (t == 0) {
        int run = 0;
        for (int b = 0; b < SCAN_B; b++) { int v = s[b]; s[b] = run; run += v; }
        g_row[N_NODES] = run;
    }
    __syncthreads();
    if (t < SCAN_B) g_boff[t] = s[t];
}
__global__ __launch_bounds__(1024) void k_scan3() {
    int i = blockIdx.x * 1024 + threadIdx.x;
    if (i < N_NODES) g_row[i] += g_boff[blockIdx.x];
}
__global__ void k_fill(const void* __restrict__ ei) {
    int e = blockIdx.x * blockDim.x + threadIdx.x;
    if (e >= E_EDGES) return;
    int s = edge_at(ei, e);
    int d = edge_at(ei, (long long)E_EDGES + e);
    int pos = g_row[d] + atomicAdd(&g_cur[d], 1);
    g_col[pos] = s;
    g_nrm[pos] = g_dinv[s] * g_dinv[d];
}

// ---------------- W -> fragment-order bf16 precompute (16 ktiles: Wh then Wl) ----------
__global__ void k_wt(const float* __restrict__ W1, const float* __restrict__ W2,
                     const float* __restrict__ W3) {
    int idx = blockIdx.x * 256 + threadIdx.x;
    int layer; const float* W; int li, NT, outf;
    if (idx < 16384)      { layer = 0; li = idx;         NT = 16; outf = 128; W = W1; }
    else if (idx < 32768) { layer = 1; li = idx - 16384; NT = 16; outf = 128; W = W2; }
    else if (idx < 40960) { layer = 2; li = idx - 32768; NT = 8;  outf = 64;  W = W3; }
    else return;
    int ktile = li / (NT * 64);
    int rem   = li % (NT * 64);
    int ntile = rem / 64;
    int r2    = rem % 64;
    int lane  = r2 >> 1;
    int reg   = r2 & 1;
    int seg   = ktile >> 3;
    int kk    = (ktile & 7) * 16 + (lane & 3) * 2 + reg * 8;
    int n0    = ntile * 8 + (lane >> 2);
    float w0 = W[(size_t)kk * outf + n0];
    float w1 = W[(size_t)(kk + 1) * outf + n0];
    __nv_bfloat16 h0, l0, h1, l1;
    hilo(w0, h0, l0);
    hilo(w1, h1, l1);
    g_wf[layer][li] = (seg == 1) ? pack2(l0, l1) : pack2(h0, h1);
}

// ---------------- HMMA GEMM: h = act(A[N,128]) @ W  (bf16 hi/lo, 3-pass issue) --------
// 256 threads, BM=128. Warp w: m-tiles (w&3)*16 and +64; n-range (w>>2)*OUTF/2.
// Per kt8: load all A/B frags, then 3 passes x 2*NW independent MMAs (dep distance 16).
template<int OUTF, bool RELU, bool EXTA>
__global__ __launch_bounds__(256) void k_mma_gemm(const float* __restrict__ Aext, int layer)
{
    const float* A = EXTA ? Aext : (const float*)g_agg;
    constexpr int NTT = OUTF / 8;
    constexpr int NW  = OUTF / 16;
    constexpr int ASZ = 128 * 68;

    extern __shared__ uint32_t smem[];
    uint32_t* AsH = smem;
    uint32_t* AsL = smem + ASZ;
    uint32_t* BF  = smem + 2 * ASZ;

    const int tid  = threadIdx.x;
    const int wid  = tid >> 5;
    const int lane = tid & 31;
    const int row0 = blockIdx.x * 128;

    // ---- A convert: thread t handles row t/2, half t&1 ----
    {
        const int r    = tid >> 1;
        const int gr   = row0 + r;
        const int qb   = (tid & 1) * 16;
        const bool ok  = (gr < N_NODES);
        const float4* arow = (const float4*)&A[(size_t)gr * 128];
        #pragma unroll
        for (int q = 0; q < 16; q++) {
            float4 v = ok ? arow[qb + q] : make_float4(0.f, 0.f, 0.f, 0.f);
            if (RELU) {
                v.x = fmaxf(v.x, 0.f); v.y = fmaxf(v.y, 0.f);
                v.z = fmaxf(v.z, 0.f); v.w = fmaxf(v.w, 0.f);
            }
            __nv_bfloat16 hx, lx, hy, ly, hz, lz, hw, lw;
            hilo(v.x, hx, lx); hilo(v.y, hy, ly);
            hilo(v.z, hz, lz); hilo(v.w, hw, lw);
            int o = r * 68 + (qb + q) * 2;
            AsH[o]     = pack2(hx, hy);
            AsH[o + 1] = pack2(hz, hw);
            AsL[o]     = pack2(lx, ly);
            AsL[o + 1] = pack2(lz, lw);
        }
    }
    // ---- B frags: bulk copy (16 ktiles) ----
    {
        const int4* src = (const int4*)g_wf[layer];
        int4* dst = (int4*)BF;
        constexpr int C4 = 16 * NTT * 64 / 4;
        #pragma unroll
        for (int i = tid; i < C4; i += 256) dst[i] = src[i];
    }
    __syncthreads();

    // ---- mainloop ----
    const int mrow0 = (wid & 3) * 16;
    const int nt0   = (wid >> 2) * NW;
    const int gr4   = lane >> 2;
    const int kq    = lane & 3;

    float acc[2][NW][4];
    #pragma unroll
    for (int m = 0; m < 2; m++)
        #pragma unroll
        for (int j = 0; j < NW; j++)
            #pragma unroll
            for (int c = 0; c < 4; c++) acc[m][j][c] = 0.f;

    #pragma unroll
    for (int kt8 = 0; kt8 < 8; kt8++) {
        const int kb = kt8 * 8;
        uint32_t ah[2][4], al[2][4];
        #pragma unroll
        for (int m = 0; m < 2; m++) {
            const int base = (mrow0 + m * 64 + gr4) * 68 + kb + kq;
            ah[m][0] = AsH[base];
            ah[m][1] = AsH[base + 8 * 68];
            ah[m][2] = AsH[base + 4];
            ah[m][3] = AsH[base + 8 * 68 + 4];
            al[m][0] = AsL[base];
            al[m][1] = AsL[base + 8 * 68];
            al[m][2] = AsL[base + 4];
            al[m][3] = AsL[base + 8 * 68 + 4];
        }
        uint2 bh[NW], bl[NW];
        #pragma unroll
        for (int j = 0; j < NW; j++) {
            const int nt = nt0 + j;
            bh[j] = *(const uint2*)&BF[((kt8 * NTT + nt) * 32 + lane) * 2];
            bl[j] = *(const uint2*)&BF[(((8 + kt8) * NTT + nt) * 32 + lane) * 2];
        }
        // pass 1: Ah@Wh  (2*NW independent accumulators)
        #pragma unroll
        for (int j = 0; j < NW; j++) {
            MMA16816(acc[0][j], ah[0], bh[j].x, bh[j].y);
            MMA16816(acc[1][j], ah[1], bh[j].x, bh[j].y);
        }
        // pass 2: Ah@Wl
        #pragma unroll
        for (int j = 0; j < NW; j++) {
            MMA16816(acc[0][j], ah[0], bl[j].x, bl[j].y);
            MMA16816(acc[1][j], ah[1], bl[j].x, bl[j].y);
        }
        // pass 3: Al@Wh
        #pragma unroll
        for (int j = 0; j < NW; j++) {
            MMA16816(acc[0][j], al[0], bh[j].x, bh[j].y);
            MMA16816(acc[1][j], al[1], bh[j].x, bh[j].y);
        }
    }

    // ---- epilogue: OUTF=128 -> fp16 only; OUTF=64 -> fp32 ----
    #pragma unroll
    for (int m = 0; m < 2; m++) {
        const int r0g = row0 + mrow0 + m * 64 + gr4;
        const int r1g = r0g + 8;
        #pragma unroll
        for (int j = 0; j < NW; j++) {
            const int col = (nt0 + j) * 8 + kq * 2;
            if constexpr (OUTF == 128) {
                if (r0g < N_NODES)
                    *(__half2*)&g_h16[(size_t)r0g * 128 + col] =
                        __float22half2_rn(make_float2(acc[m][j][0], acc[m][j][1]));
                if (r1g < N_NODES)
                    *(__half2*)&g_h16[(size_t)r1g * 128 + col] =
                        __float22half2_rn(make_float2(acc[m][j][2], acc[m][j][3]));
            } else {
                if (r0g < N_NODES)
                    *(float2*)&g_h[(size_t)r0g * OUTF + col] =
                        make_float2(acc[m][j][0], acc[m][j][1]);
                if (r1g < N_NODES)
                    *(float2*)&g_h[(size_t)r1g * OUTF + col] =
                        make_float2(acc[m][j][2], acc[m][j][3]);
            }
        }
    }
}

// ---------------- gather-side aggregation: one warp per node, 4-edge pipelined ----------
template<int F, bool EXTO>
__global__ __launch_bounds__(256) void k_agg(const float* __restrict__ b,
                                             float* __restrict__ Oext)
{
    float* out = EXTO ? Oext : (float*)g_agg;
    const int w = (blockIdx.x * 256 + threadIdx.x) >> 5;
    const int lane = threadIdx.x & 31;
    if (w >= N_NODES) return;

    const float di = g_dinv[w];
    const float sw = di * di;
    int e = g_row[w];
    const int end = g_row[w + 1];

    if constexpr (F == 128) {
        const uint2* hg = (const uint2*)g_h16;
        uint2 rs = hg[(size_t)w * 32 + lane];
        float2 s0f = __half22float2(*(const __half2*)&rs.x);
        float2 s1f = __half22float2(*(const __half2*)&rs.y);
        float4 bv = *(const float4*)&b[lane * 4];
        float ax = fmaf(s0f.x, sw, bv.x), ay = fmaf(s0f.y, sw, bv.y);
        float az = fmaf(s1f.x, sw, bv.z), aw = fmaf(s1f.y, sw, bv.w);

        for (; e + 3 < end; e += 4) {
            int s0 = __ldg(&g_col[e + 0]);
            int s1 = __ldg(&g_col[e + 1]);
            int s2 = __ldg(&g_col[e + 2]);
            int s3 = __ldg(&g_col[e + 3]);
            float w0 = __ldg(&g_nrm[e + 0]);
            float w1 = __ldg(&g_nrm[e + 1]);
            float w2 = __ldg(&g_nrm[e + 2]);
            float w3 = __ldg(&g_nrm[e + 3]);
            uint2 r0 = hg[(size_t)s0 * 32 + lane];
            uint2 r1 = hg[(size_t)s1 * 32 + lane];
            uint2 r2 = hg[(size_t)s2 * 32 + lane];
            uint2 r3 = hg[(size_t)s3 * 32 + lane];
            float2 p0 = __half22float2(*(const __half2*)&r0.x);
            float2 p1 = __half22float2(*(const __half2*)&r0.y);
            ax = fmaf(p0.x, w0, ax); ay = fmaf(p0.y, w0, ay);
            az = fmaf(p1.x, w0, az); aw = fmaf(p1.y, w0, aw);
            p0 = __half22float2(*(const __half2*)&r1.x);
            p1 = __half22float2(*(const __half2*)&r1.y);
            ax = fmaf(p0.x, w1, ax); ay = fmaf(p0.y, w1, ay);
            az = fmaf(p1.x, w1, az); aw = fmaf(p1.y, w1, aw);
            p0 = __half22float2(*(const __half2*)&r2.x);
            p1 = __half22float2(*(const __half2*)&r2.y);
            ax = fmaf(p0.x, w2, ax); ay = fmaf(p0.y, w2, ay);
            az = fmaf(p1.x, w2, az); aw = fmaf(p1.y, w2, aw);
            p0 = __half22float2(*(const __half2*)&r3.x);
            p1 = __half22float2(*(const __half2*)&r3.y);
            ax = fmaf(p0.x, w3, ax); ay = fmaf(p0.y, w3, ay);
            az = fmaf(p1.x, w3, az); aw = fmaf(p1.y, w3, aw);
        }
        for (; e < end; e++) {
            int s0 = __ldg(&g_col[e]);
            float w0 = __ldg(&g_nrm[e]);
            uint2 r0 = hg[(size_t)s0 * 32 + lane];
            float2 p0 = __half22float2(*(const __half2*)&r0.x);
            float2 p1 = __half22float2(*(const __half2*)&r0.y);
            ax = fmaf(p0.x, w0, ax); ay = fmaf(p0.y, w0, ay);
            az = fmaf(p1.x, w0, az); aw = fmaf(p1.y, w0, aw);
        }
        *(float4*)&out[(size_t)w * 128 + lane * 4] = make_float4(ax, ay, az, aw);
    } else {
        const float2* h2 = (const float2*)g_h;
        float2 hv = h2[(size_t)w * 32 + lane];
        float2 bv = *(const float2*)&b[lane * 2];
        float ax = fmaf(hv.x, sw, bv.x), ay = fmaf(hv.y, sw, bv.y);
        for (; e + 3 < end; e += 4) {
            int s0 = __ldg(&g_col[e + 0]);
            int s1 = __ldg(&g_col[e + 1]);
            int s2 = __ldg(&g_col[e + 2]);
            int s3 = __ldg(&g_col[e + 3]);
            float w0 = __ldg(&g_nrm[e + 0]);
            float w1 = __ldg(&g_nrm[e + 1]);
            float w2 = __ldg(&g_nrm[e + 2]);
            float w3 = __ldg(&g_nrm[e + 3]);
            float2 v0 = h2[(size_t)s0 * 32 + lane];
            float2 v1 = h2[(size_t)s1 * 32 + lane];
            float2 v2 = h2[(size_t)s2 * 32 + lane];
            float2 v3 = h2[(size_t)s3 * 32 + lane];
            ax = fmaf(v0.x, w0, ax); ay = fmaf(v0.y, w0, ay);
            ax = fmaf(v1.x, w1, ax); ay = fmaf(v1.y, w1, ay);
            ax = fmaf(v2.x, w2, ax); ay = fmaf(v2.y, w2, ay);
            ax = fmaf(v3.x, w3, ax); ay = fmaf(v3.y, w3, ay);
        }
        for (; e < end; e++) {
            int s0 = __ldg(&g_col[e]);
            float w0 = __ldg(&g_nrm[e]);
            float2 v0 = h2[(size_t)s0 * 32 + lane];
            ax = fmaf(v0.x, w0, ax); ay = fmaf(v0.y, w0, ay);
        }
        *(float2*)&out[(size_t)w * 64 + lane * 2] = make_float2(ax, ay);
    }
}

// ---------------- host ----------------
extern "C" void kernel_launch(void* const* d_in, const int* in_sizes, int n_in,
                              void* d_out, int out_size)
{
    const float* x  = (const float*)d_in[0];
    const void*  ei = d_in[1];
    const float* W1 = (const float*)d_in[2];
    const float* b1 = (const float*)d_in[3];
    const float* W2 = (const float*)d_in[4];
    const float* b2 = (const float*)d_in[5];
    const float* W3 = (const float*)d_in[6];
    const float* b3 = (const float*)d_in[7];
    float* out = (float*)d_out;

    const int TB = 256;
    const int gN    = (N_NODES + TB - 1) / TB;
    const int gE    = (E_EDGES + TB - 1) / TB;
    const int gemmG = (N_NODES + 127) / 128;
    const int aggG  = (N_NODES * 32 + TB - 1) / TB;

    constexpr int ASZ_B = 128 * 68 * 4;
    constexpr int SMEM128 = 2 * ASZ_B + 16 * 16 * 64 * 4;  // 135168
    constexpr int SMEM64  = 2 * ASZ_B + 16 * 8 * 64 * 4;   // 102400
    cudaFuncSetAttribute(k_mma_gemm<F_HID, false, true>,
                         cudaFuncAttributeMaxDynamicSharedMemorySize, SMEM128);
    cudaFuncSetAttribute(k_mma_gemm<F_HID, true, false>,
                         cudaFuncAttributeMaxDynamicSharedMemorySize, SMEM128);
    cudaFuncSetAttribute(k_mma_gemm<F_OUT, true, false>,
                         cudaFuncAttributeMaxDynamicSharedMemorySize, SMEM64);

    // gemm1 kept 4th — the ncu window captures it.
    k_detect<<<1, 32>>>((const int*)ei);
    k_zero<<<gN, TB>>>();
    k_wt<<<160, 256>>>(W1, W2, W3);
    k_mma_gemm<F_HID, false, true><<<gemmG, 256, SMEM128>>>(x, 0);   // layer-1 GEMM (profiled)

    // CSR build
    k_hist<<<gE, TB>>>(ei);
    k_scan1<<<SCAN_B, 1024>>>();
    k_scan2<<<1, 128>>>();
    k_scan3<<<SCAN_B, 1024>>>();
    k_fill<<<gE, TB>>>(ei);

    // layer 1 aggregation
    k_agg<F_HID, false><<<aggG, TB>>>(b1, nullptr);
    // layer 2
    k_mma_gemm<F_HID, true, false><<<gemmG, 256, SMEM128>>>(nullptr, 1);
    k_agg<F_HID, false><<<aggG, TB>>>(b2, nullptr);
    // layer 3
    k_mma_gemm<F_OUT, true, false><<<gemmG, 256, SMEM64>>>(nullptr, 2);
    k_agg<F_OUT, true><<<aggG, TB>>>(b3, out);

    (void)n_in; (void)out_size; (void)in_sizes;
}

// round 15
// speedup vs baseline: 1.1051x; 1.1051x over previous
#include <cuda_runtime.h>
#include <cuda_bf16.h>
#include <cuda_fp16.h>
#include <stdint.h>

#define N_NODES 100000
#define E_EDGES 1600000
#define F_HID   128
#define F_OUT   64
#define SCAN_B  98   // ceil(N_NODES / 1024)

// ---------------- scratch (static device arrays; no allocations) ----------------
__device__ __align__(256) float  g_h[(size_t)N_NODES * F_HID];    // fp32 h (layer 3 only)
__device__ __align__(256) __half g_h16[(size_t)N_NODES * F_HID];  // fp16 h (layers 1-2)
__device__ __align__(256) float  g_agg[(size_t)N_NODES * F_HID];
__device__ __align__(256) float  g_dinv[N_NODES];
__device__ __align__(256) uint2  g_meta[E_EDGES];                 // {src, nrm bits} per edge
__device__ __align__(256) int    g_row[N_NODES + 1];
__device__ __align__(256) int    g_deg_i[N_NODES];
__device__ __align__(256) int    g_cur[N_NODES];
__device__ __align__(256) int    g_bsum[SCAN_B];
__device__ __align__(256) int    g_boff[SCAN_B];
// W in mma-fragment order, 16 ktiles (0-7: Wh, 8-15: Wl). Read via __ldg in mainloop.
__device__ __align__(256) unsigned g_wf[3][16 * 16 * 64];
__device__ int g_is64;

__device__ __forceinline__ void hilo(float w, __nv_bfloat16& h, __nv_bfloat16& l) {
    h = __float2bfloat16(w);
    l = __float2bfloat16(w - __bfloat162float(h));
}
__device__ __forceinline__ uint32_t pack2(__nv_bfloat16 a, __nv_bfloat16 b) {
    return ((uint32_t)__bfloat16_as_ushort(b) << 16) | __bfloat16_as_ushort(a);
}

#define MMA16816(acc, a, bx, by) \
    asm volatile( \
        "mma.sync.aligned.m16n8k16.row.col.f32.bf16.bf16.f32 " \
        "{%0,%1,%2,%3}, {%4,%5,%6,%7}, {%8,%9}, {%0,%1,%2,%3};" \
        : "+f"((acc)[0]), "+f"((acc)[1]), "+f"((acc)[2]), "+f"((acc)[3]) \
        : "r"((a)[0]), "r"((a)[1]), "r"((a)[2]), "r"((a)[3]), "r"(bx), "r"(by))

// ---------------- edge dtype detection ----------------
__global__ void k_detect(const int* __restrict__ w) {
    int lane = threadIdx.x;
    int acc = 0;
    for (int i = 1 + 2 * lane; i < 4096; i += 64) acc |= w[i];
    #pragma unroll
    for (int o = 16; o; o >>= 1) acc |= __shfl_xor_sync(0xffffffffu, acc, o);
    if (lane == 0) g_is64 = (acc == 0) ? 1 : 0;
}
__device__ __forceinline__ int edge_at(const void* ei, long long idx) {
    int v = g_is64 ? (int)((const long long*)ei)[idx] : ((const int*)ei)[idx];
    v = v < 0 ? 0 : v;
    return v >= N_NODES ? N_NODES - 1 : v;
}

// ---------------- CSR build ----------------
__global__ void k_zero() {
    int i = blockIdx.x * blockDim.x + threadIdx.x;
    if (i < N_NODES) { g_deg_i[i] = 0; g_cur[i] = 0; }
}
__global__ void k_hist(const void* __restrict__ ei) {
    int e = blockIdx.x * blockDim.x + threadIdx.x;
    if (e < E_EDGES) atomicAdd(&g_deg_i[edge_at(ei, (long long)E_EDGES + e)], 1);
}
__global__ __launch_bounds__(1024) void k_scan1() {
    const int t = threadIdx.x;
    const int i = blockIdx.x * 1024 + t;
    const int lane = t & 31, warp = t >> 5;
    int d = (i < N_NODES) ? g_deg_i[i] : 0;
    int v = d;
    #pragma unroll
    for (int o = 1; o < 32; o <<= 1) {
        int n = __shfl_up_sync(0xffffffffu, v, o);
        if (lane >= o) v += n;
    }
    __shared__ int wsum[32];
    if (lane == 31) wsum[warp] = v;
    __syncthreads();
    if (warp == 0) {
        int s = wsum[lane];
        #pragma unroll
        for (int o = 1; o < 32; o <<= 1) {
            int n = __shfl_up_sync(0xffffffffu, s, o);
            if (lane >= o) s += n;
        }
        wsum[lane] = s;
    }
    __syncthreads();
    int excl = v - d + (warp > 0 ? wsum[warp - 1] : 0);
    if (i < N_NODES) {
        g_row[i] = excl;
        g_dinv[i] = rsqrtf((float)(d + 1));
    }
    if (t == 1023) g_bsum[blockIdx.x] = excl + d;
}
__global__ void k_scan2() {
    __shared__ int s[SCAN_B];
    int t = threadIdx.x;
    if (t < SCAN_B) s[t] = g_bsum[t];
    __syncthreads();
    if (t == 0) {
        int run = 0;
        for (int b = 0; b < SCAN_B; b++) { int v = s[b]; s[b] = run; run += v; }
        g_row[N_NODES] = run;
    }
    __syncthreads();
    if (t < SCAN_B) g_boff[t] = s[t];
}
__global__ __launch_bounds__(1024) void k_scan3() {
    int i = blockIdx.x * 1024 + threadIdx.x;
    if (i < N_NODES) g_row[i] += g_boff[blockIdx.x];
}
__global__ void k_fill(const void* __restrict__ ei) {
    int e = blockIdx.x * blockDim.x + threadIdx.x;
    if (e >= E_EDGES) return;
    int s = edge_at(ei, e);
    int d = edge_at(ei, (long long)E_EDGES + e);
    int pos = g_row[d] + atomicAdd(&g_cur[d], 1);
    float nrm = g_dinv[s] * g_dinv[d];
    g_meta[pos] = make_uint2((unsigned)s, __float_as_uint(nrm));
}

// ---------------- W -> fragment-order bf16 precompute (16 ktiles: Wh then Wl) ----------
__global__ void k_wt(const float* __restrict__ W1, const float* __restrict__ W2,
                     const float* __restrict__ W3) {
    int idx = blockIdx.x * 256 + threadIdx.x;
    int layer; const float* W; int li, NT, outf;
    if (idx < 16384)      { layer = 0; li = idx;         NT = 16; outf = 128; W = W1; }
    else if (idx < 32768) { layer = 1; li = idx - 16384; NT = 16; outf = 128; W = W2; }
    else if (idx < 40960) { layer = 2; li = idx - 32768; NT = 8;  outf = 64;  W = W3; }
    else return;
    int ktile = li / (NT * 64);
    int rem   = li % (NT * 64);
    int ntile = rem / 64;
    int r2    = rem % 64;
    int lane  = r2 >> 1;
    int reg   = r2 & 1;
    int seg   = ktile >> 3;
    int kk    = (ktile & 7) * 16 + (lane & 3) * 2 + reg * 8;
    int n0    = ntile * 8 + (lane >> 2);
    float w0 = W[(size_t)kk * outf + n0];
    float w1 = W[(size_t)(kk + 1) * outf + n0];
    __nv_bfloat16 h0, l0, h1, l1;
    hilo(w0, h0, l0);
    hilo(w1, h1, l1);
    g_wf[layer][li] = (seg == 1) ? pack2(l0, l1) : pack2(h0, h1);
}

// ---------------- HMMA GEMM: h = act(A[N,128]) @ W  (bf16 hi/lo, B via L1 LDG) --------
// 256 threads, BM=128, 2 CTAs/SM (smem = A only, 68KB). Warp w: m-tiles (w&3)*16, +64;
// n-range (w>>2)*OUTF/2. B frags read via __ldg (shared across all CTAs -> L1 hits).
template<int OUTF, bool RELU, bool EXTA>
__global__ __launch_bounds__(256, 2) void k_mma_gemm(const float* __restrict__ Aext, int layer)
{
    const float* A = EXTA ? Aext : (const float*)g_agg;
    constexpr int NTT = OUTF / 8;
    constexpr int NW  = OUTF / 16;
    constexpr int ASZ = 128 * 68;

    extern __shared__ uint32_t smem[];
    uint32_t* AsH = smem;
    uint32_t* AsL = smem + ASZ;

    const int tid  = threadIdx.x;
    const int wid  = tid >> 5;
    const int lane = tid & 31;
    const int row0 = blockIdx.x * 128;

    // ---- A convert: thread t handles row t/2, half t&1 ----
    {
        const int r    = tid >> 1;
        const int gr   = row0 + r;
        const int qb   = (tid & 1) * 16;
        const bool ok  = (gr < N_NODES);
        const float4* arow = (const float4*)&A[(size_t)gr * 128];
        #pragma unroll
        for (int q = 0; q < 16; q++) {
            float4 v = ok ? arow[qb + q] : make_float4(0.f, 0.f, 0.f, 0.f);
            if (RELU) {
                v.x = fmaxf(v.x, 0.f); v.y = fmaxf(v.y, 0.f);
                v.z = fmaxf(v.z, 0.f); v.w = fmaxf(v.w, 0.f);
            }
            __nv_bfloat16 hx, lx, hy, ly, hz, lz, hw, lw;
            hilo(v.x, hx, lx); hilo(v.y, hy, ly);
            hilo(v.z, hz, lz); hilo(v.w, hw, lw);
            int o = r * 68 + (qb + q) * 2;
            AsH[o]     = pack2(hx, hy);
            AsH[o + 1] = pack2(hz, hw);
            AsL[o]     = pack2(lx, ly);
            AsL[o + 1] = pack2(lz, lw);
        }
    }
    __syncthreads();

    // ---- mainloop ----
    const int mrow0 = (wid & 3) * 16;
    const int nt0   = (wid >> 2) * NW;
    const int gr4   = lane >> 2;
    const int kq    = lane & 3;
    const uint2* __restrict__ BW = (const uint2*)g_wf[layer];

    float acc[2][NW][4];
    #pragma unroll
    for (int m = 0; m < 2; m++)
        #pragma unroll
        for (int j = 0; j < NW; j++)
            #pragma unroll
            for (int c = 0; c < 4; c++) acc[m][j][c] = 0.f;

    #pragma unroll
    for (int kt8 = 0; kt8 < 8; kt8++) {
        const int kb = kt8 * 8;
        uint32_t ah[2][4], al[2][4];
        #pragma unroll
        for (int m = 0; m < 2; m++) {
            const int base = (mrow0 + m * 64 + gr4) * 68 + kb + kq;
            ah[m][0] = AsH[base];
            ah[m][1] = AsH[base + 8 * 68];
            ah[m][2] = AsH[base + 4];
            ah[m][3] = AsH[base + 8 * 68 + 4];
            al[m][0] = AsL[base];
            al[m][1] = AsL[base + 8 * 68];
            al[m][2] = AsL[base + 4];
            al[m][3] = AsL[base + 8 * 68 + 4];
        }
        // pass 1: Ah@Wh (cache bh frags in regs for pass 3)
        uint2 bh[NW];
        #pragma unroll
        for (int j = 0; j < NW; j++) {
            bh[j] = __ldg(&BW[(kt8 * NTT + nt0 + j) * 32 + lane]);
            MMA16816(acc[0][j], ah[0], bh[j].x, bh[j].y);
            MMA16816(acc[1][j], ah[1], bh[j].x, bh[j].y);
        }
        // pass 2: Ah@Wl (stream bl)
        #pragma unroll
        for (int j = 0; j < NW; j++) {
            uint2 bl = __ldg(&BW[((8 + kt8) * NTT + nt0 + j) * 32 + lane]);
            MMA16816(acc[0][j], ah[0], bl.x, bl.y);
            MMA16816(acc[1][j], ah[1], bl.x, bl.y);
        }
        // pass 3: Al@Wh (reuse bh regs)
        #pragma unroll
        for (int j = 0; j < NW; j++) {
            MMA16816(acc[0][j], al[0], bh[j].x, bh[j].y);
            MMA16816(acc[1][j], al[1], bh[j].x, bh[j].y);
        }
    }

    // ---- epilogue: OUTF=128 -> fp16 only; OUTF=64 -> fp32 ----
    #pragma unroll
    for (int m = 0; m < 2; m++) {
        const int r0g = row0 + mrow0 + m * 64 + gr4;
        const int r1g = r0g + 8;
        #pragma unroll
        for (int j = 0; j < NW; j++) {
            const int col = (nt0 + j) * 8 + kq * 2;
            if constexpr (OUTF == 128) {
                if (r0g < N_NODES)
                    *(__half2*)&g_h16[(size_t)r0g * 128 + col] =
                        __float22half2_rn(make_float2(acc[m][j][0], acc[m][j][1]));
                if (r1g < N_NODES)
                    *(__half2*)&g_h16[(size_t)r1g * 128 + col] =
                        __float22half2_rn(make_float2(acc[m][j][2], acc[m][j][3]));
            } else {
                if (r0g < N_NODES)
                    *(float2*)&g_h[(size_t)r0g * OUTF + col] =
                        make_float2(acc[m][j][0], acc[m][j][1]);
                if (r1g < N_NODES)
                    *(float2*)&g_h[(size_t)r1g * OUTF + col] =
                        make_float2(acc[m][j][2], acc[m][j][3]);
            }
        }
    }
}

// ---------------- gather-side aggregation: one warp per node, packed meta --------------
// Per 4-edge iter: 4 LDG.64 meta + 4 gathers (was 12 LDGs) — LSU-issue bound fix.
template<int F, bool EXTO>
__global__ __launch_bounds__(256) void k_agg(const float* __restrict__ b,
                                             float* __restrict__ Oext)
{
    float* out = EXTO ? Oext : (float*)g_agg;
    const int w = (blockIdx.x * 256 + threadIdx.x) >> 5;
    const int lane = threadIdx.x & 31;
    if (w >= N_NODES) return;

    const float di = g_dinv[w];
    const float sw = di * di;
    int e = g_row[w];
    const int end = g_row[w + 1];

    if constexpr (F == 128) {
        const uint2* hg = (const uint2*)g_h16;
        uint2 rs = hg[(size_t)w * 32 + lane];
        float2 s0f = __half22float2(*(const __half2*)&rs.x);
        float2 s1f = __half22float2(*(const __half2*)&rs.y);
        float4 bv = *(const float4*)&b[lane * 4];
        float ax = fmaf(s0f.x, sw, bv.x), ay = fmaf(s0f.y, sw, bv.y);
        float az = fmaf(s1f.x, sw, bv.z), aw = fmaf(s1f.y, sw, bv.w);

        for (; e + 3 < end; e += 4) {
            uint2 m0 = __ldg(&g_meta[e + 0]);
            uint2 m1 = __ldg(&g_meta[e + 1]);
            uint2 m2 = __ldg(&g_meta[e + 2]);
            uint2 m3 = __ldg(&g_meta[e + 3]);
            uint2 r0 = hg[(size_t)m0.x * 32 + lane];
            uint2 r1 = hg[(size_t)m1.x * 32 + lane];
            uint2 r2 = hg[(size_t)m2.x * 32 + lane];
            uint2 r3 = hg[(size_t)m3.x * 32 + lane];
            float w0 = __uint_as_float(m0.y), w1 = __uint_as_float(m1.y);
            float w2 = __uint_as_float(m2.y), w3 = __uint_as_float(m3.y);
            float2 p0 = __half22float2(*(const __half2*)&r0.x);
            float2 p1 = __half22float2(*(const __half2*)&r0.y);
            ax = fmaf(p0.x, w0, ax); ay = fmaf(p0.y, w0, ay);
            az = fmaf(p1.x, w0, az); aw = fmaf(p1.y, w0, aw);
            p0 = __half22float2(*(const __half2*)&r1.x);
            p1 = __half22float2(*(const __half2*)&r1.y);
            ax = fmaf(p0.x, w1, ax); ay = fmaf(p0.y, w1, ay);
            az = fmaf(p1.x, w1, az); aw = fmaf(p1.y, w1, aw);
            p0 = __half22float2(*(const __half2*)&r2.x);
            p1 = __half22float2(*(const __half2*)&r2.y);
            ax = fmaf(p0.x, w2, ax); ay = fmaf(p0.y, w2, ay);
            az = fmaf(p1.x, w2, az); aw = fmaf(p1.y, w2, aw);
            p0 = __half22float2(*(const __half2*)&r3.x);
            p1 = __half22float2(*(const __half2*)&r3.y);
            ax = fmaf(p0.x, w3, ax); ay = fmaf(p0.y, w3, ay);
            az = fmaf(p1.x, w3, az); aw = fmaf(p1.y, w3, aw);
        }
        for (; e < end; e++) {
            uint2 m0 = __ldg(&g_meta[e]);
            uint2 r0 = hg[(size_t)m0.x * 32 + lane];
            float w0 = __uint_as_float(m0.y);
            float2 p0 = __half22float2(*(const __half2*)&r0.x);
            float2 p1 = __half22float2(*(const __half2*)&r0.y);
            ax = fmaf(p0.x, w0, ax); ay = fmaf(p0.y, w0, ay);
            az = fmaf(p1.x, w0, az); aw = fmaf(p1.y, w0, aw);
        }
        *(float4*)&out[(size_t)w * 128 + lane * 4] = make_float4(ax, ay, az, aw);
    } else {
        const float2* h2 = (const float2*)g_h;
        float2 hv = h2[(size_t)w * 32 + lane];
        float2 bv = *(const float2*)&b[lane * 2];
        float ax = fmaf(hv.x, sw, bv.x), ay = fmaf(hv.y, sw, bv.y);
        for (; e + 3 < end; e += 4) {
            uint2 m0 = __ldg(&g_meta[e + 0]);
            uint2 m1 = __ldg(&g_meta[e + 1]);
            uint2 m2 = __ldg(&g_meta[e + 2]);
            uint2 m3 = __ldg(&g_meta[e + 3]);
            float2 v0 = h2[(size_t)m0.x * 32 + lane];
            float2 v1 = h2[(size_t)m1.x * 32 + lane];
            float2 v2 = h2[(size_t)m2.x * 32 + lane];
            float2 v3 = h2[(size_t)m3.x * 32 + lane];
            ax = fmaf(v0.x, __uint_as_float(m0.y), ax); ay = fmaf(v0.y, __uint_as_float(m0.y), ay);
            ax = fmaf(v1.x, __uint_as_float(m1.y), ax); ay = fmaf(v1.y, __uint_as_float(m1.y), ay);
            ax = fmaf(v2.x, __uint_as_float(m2.y), ax); ay = fmaf(v2.y, __uint_as_float(m2.y), ay);
            ax = fmaf(v3.x, __uint_as_float(m3.y), ax); ay = fmaf(v3.y, __uint_as_float(m3.y), ay);
        }
        for (; e < end; e++) {
            uint2 m0 = __ldg(&g_meta[e]);
            float2 v0 = h2[(size_t)m0.x * 32 + lane];
            ax = fmaf(v0.x, __uint_as_float(m0.y), ax);
            ay = fmaf(v0.y, __uint_as_float(m0.y), ay);
        }
        *(float2*)&out[(size_t)w * 64 + lane * 2] = make_float2(ax, ay);
    }
}

// ---------------- host ----------------
extern "C" void kernel_launch(void* const* d_in, const int* in_sizes, int n_in,
                              void* d_out, int out_size)
{
    const float* x  = (const float*)d_in[0];
    const void*  ei = d_in[1];
    const float* W1 = (const float*)d_in[2];
    const float* b1 = (const float*)d_in[3];
    const float* W2 = (const float*)d_in[4];
    const float* b2 = (const float*)d_in[5];
    const float* W3 = (const float*)d_in[6];
    const float* b3 = (const float*)d_in[7];
    float* out = (float*)d_out;

    const int TB = 256;
    const int gN    = (N_NODES + TB - 1) / TB;
    const int gE    = (E_EDGES + TB - 1) / TB;
    const int gemmG = (N_NODES + 127) / 128;
    const int aggG  = (N_NODES * 32 + TB - 1) / TB;

    constexpr int SMEM_A = 2 * 128 * 68 * 4;   // 69632 B (A hi+lo only; B via L1)
    cudaFuncSetAttribute(k_mma_gemm<F_HID, false, true>,
                         cudaFuncAttributeMaxDynamicSharedMemorySize, SMEM_A);
    cudaFuncSetAttribute(k_mma_gemm<F_HID, true, false>,
                         cudaFuncAttributeMaxDynamicSharedMemorySize, SMEM_A);
    cudaFuncSetAttribute(k_mma_gemm<F_OUT, true, false>,
                         cudaFuncAttributeMaxDynamicSharedMemorySize, SMEM_A);

    // gemm1 kept 4th — the ncu window captures it.
    k_detect<<<1, 32>>>((const int*)ei);
    k_zero<<<gN, TB>>>();
    k_wt<<<160, 256>>>(W1, W2, W3);
    k_mma_gemm<F_HID, false, true><<<gemmG, 256, SMEM_A>>>(x, 0);   // layer-1 GEMM (profiled)

    // CSR build
    k_hist<<<gE, TB>>>(ei);
    k_scan1<<<SCAN_B, 1024>>>();
    k_scan2<<<1, 128>>>();
    k_scan3<<<SCAN_B, 1024>>>();
    k_fill<<<gE, TB>>>(ei);

    // layer 1 aggregation
    k_agg<F_HID, false><<<aggG, TB>>>(b1, nullptr);
    // layer 2
    k_mma_gemm<F_HID, true, false><<<gemmG, 256, SMEM_A>>>(nullptr, 1);
    k_agg<F_HID, false><<<aggG, TB>>>(b2, nullptr);
    // layer 3
    k_mma_gemm<F_OUT, true, false><<<gemmG, 256, SMEM_A>>>(nullptr, 2);
    k_agg<F_OUT, true><<<aggG, TB>>>(b3, out);

    (void)n_in; (void)out_size; (void)in_sizes;
}